// round 10
// baseline (speedup 1.0000x reference)
#include <cuda_runtime.h>
#include <cuda_bf16.h>
#include <cstddef>

#define NN   8192
#define TS   64
#define NOUT 128

// ---------------- scratch (device globals: no allocation allowed) ----------
__device__ float g_adj[(size_t)NN * NN];     // 256 MB
__device__ float g_H1[(size_t)NN * NOUT];
__device__ float g_U1[(size_t)NN * NOUT];
__device__ float g_H2[(size_t)NN * NOUT];

// ---------------- zero kernel ----------------------------------------------
__global__ void k_zero(float* __restrict__ p, int n) {
    int i = blockIdx.x * 256 + threadIdx.x;
    if (i < n) p[i] = 0.f;
}

// ---------------- pass 1: adj build + fused A@token -------------------------
// Grid (128,128); CTA handles unordered tile pair {I,J}, J>=I.
// Reads each A element exactly once; writes adj[I,J] and adj[J,I].
__global__ __launch_bounds__(256) void k_build(
    const float* __restrict__ A1, const float* __restrict__ A2, const float* __restrict__ A3,
    const float* __restrict__ T1, const float* __restrict__ T2, const float* __restrict__ T3,
    const float* __restrict__ wb, float* __restrict__ feat_out)
{
    int I = blockIdx.y, J = blockIdx.x;
    if (J < I) return;

    __shared__ float sT1[TS][TS + 1];
    __shared__ float sT2[TS][TS + 1];
    __shared__ float tokJ[3][TS][10];
    __shared__ float tokI[3][TS][10];

    int tid = threadIdx.x;
    int Ig = I * TS, Jg = J * TS;
    const float* Aks[3] = {A1, A2, A3};
    const float* Tks[3] = {T1, T2, T3};
    float wk3[3] = {wb[0], wb[1], wb[2]};

    // stage token rows for both tile row-ranges
    for (int idx = tid; idx < 3 * TS * 10; idx += 256) {
        int k = idx / (TS * 10);
        int rem = idx % (TS * 10);
        int row = rem / 10, t = rem % 10;
        tokJ[k][row][t] = Tks[k][(Jg + row) * 10 + t];
        tokI[k][row][t] = Tks[k][(Ig + row) * 10 + t];
    }
    __syncthreads();

    int r = tid >> 2;        // row within tile (0..63)
    int q = tid & 3;         // column quadrant; thread handles cols q+4*yy
    bool diag = (I == J);

    // ---- side A: block (I,J) rows Ig+r, cols Jg+* ----
    {
        float tval[16];
        #pragma unroll
        for (int yy = 0; yy < 16; yy++) tval[yy] = 0.f;
        #pragma unroll
        for (int k = 0; k < 3; k++) {
            const float* rowp = Aks[k] + (size_t)(Ig + r) * NN + Jg + q;
            float wk = wk3[k];
            float ft[10];
            #pragma unroll
            for (int t = 0; t < 10; t++) ft[t] = 0.f;
            #pragma unroll
            for (int yy = 0; yy < 16; yy++) {
                int y = q + 4 * yy;
                float a = rowp[4 * yy];
                tval[yy] += wk * a;
                #pragma unroll
                for (int t = 0; t < 10; t++) ft[t] += a * tokJ[k][y][t];
            }
            #pragma unroll
            for (int t = 0; t < 10; t++) {
                float v = ft[t];
                v += __shfl_down_sync(0xffffffffu, v, 2, 4);
                v += __shfl_down_sync(0xffffffffu, v, 1, 4);
                if (q == 0)
                    atomicAdd(&feat_out[(size_t)k * NN * 10 + (size_t)(Ig + r) * 10 + t], v);
            }
        }
        #pragma unroll
        for (int yy = 0; yy < 16; yy++) sT1[r][q + 4 * yy] = tval[yy];
    }

    // ---- side B: block (J,I) rows Jg+r, cols Ig+* (skip on diagonal) ----
    if (!diag) {
        float tval[16];
        #pragma unroll
        for (int yy = 0; yy < 16; yy++) tval[yy] = 0.f;
        #pragma unroll
        for (int k = 0; k < 3; k++) {
            const float* rowp = Aks[k] + (size_t)(Jg + r) * NN + Ig + q;
            float wk = wk3[k];
            float ft[10];
            #pragma unroll
            for (int t = 0; t < 10; t++) ft[t] = 0.f;
            #pragma unroll
            for (int yy = 0; yy < 16; yy++) {
                int y = q + 4 * yy;
                float a = rowp[4 * yy];
                tval[yy] += wk * a;
                #pragma unroll
                for (int t = 0; t < 10; t++) ft[t] += a * tokI[k][y][t];
            }
            #pragma unroll
            for (int t = 0; t < 10; t++) {
                float v = ft[t];
                v += __shfl_down_sync(0xffffffffu, v, 2, 4);
                v += __shfl_down_sync(0xffffffffu, v, 1, 4);
                if (q == 0)
                    atomicAdd(&feat_out[(size_t)k * NN * 10 + (size_t)(Jg + r) * 10 + t], v);
            }
        }
        #pragma unroll
        for (int yy = 0; yy < 16; yy++) sT2[r][q + 4 * yy] = tval[yy];
    }
    __syncthreads();

    // ---- write adj tiles (coalesced; transposed reads via padded smem) ----
    int y = tid & 63, xb = tid >> 6;
    if (diag) {
        #pragma unroll
        for (int i = 0; i < 16; i++) {
            int x = xb + 4 * i;
            g_adj[(size_t)(Ig + x) * NN + Jg + y] = sT1[x][y] + sT1[y][x];
        }
    } else {
        #pragma unroll
        for (int i = 0; i < 16; i++) {
            int x = xb + 4 * i;
            g_adj[(size_t)(Ig + x) * NN + Jg + y] = sT1[x][y] + sT2[y][x];
            g_adj[(size_t)(Jg + x) * NN + Ig + y] = sT2[x][y] + sT1[y][x];
        }
    }
}

// ---------------- generic fp32 SGEMM body (64x64 tile, K-step 32) -----------
// C[M x 128] = A[M x K] @ B[K x 128], optional +bias[col], optional
// C = 0.5*(C + comb) combine. Grid: (M/64, 2). 256 threads, 4x4 per thread.
__device__ __forceinline__ void gemm_body(
    const float* __restrict__ A, int lda, int K,
    const float* __restrict__ B,
    const float* __restrict__ bias,
    const float* __restrict__ comb,
    float* __restrict__ C)
{
    __shared__ float sA[64][33];
    __shared__ float sB[32][68];

    int tid = threadIdx.x;
    int rowBase = blockIdx.x * 64;
    int cBase   = blockIdx.y * 64;

    float acc[4][4];
    #pragma unroll
    for (int i = 0; i < 4; i++)
        #pragma unroll
        for (int j = 0; j < 4; j++) acc[i][j] = 0.f;

    int tr = tid >> 4;       // 0..15 : owns rows tr + 16*i
    int tc = tid & 15;       // 0..15 : owns cols tc*4 .. tc*4+3 (local)

    int la_r  = tid >> 2;          // 0..63
    int la_k4 = (tid & 3) * 4;     // 0,4,8,12
    int lb_c4 = (tid & 15) * 4;    // 0..60
    int lb_k  = tid >> 4;          // 0..15

    for (int k0 = 0; k0 < K; k0 += 32) {
        const float* ap = A + (size_t)(rowBase + la_r) * lda + k0 + la_k4;
        float4 a0 = *(const float4*)(ap);
        float4 a1 = *(const float4*)(ap + 16);
        const float* bp = B + (size_t)(k0 + lb_k) * 128 + cBase + lb_c4;
        float4 b0 = *(const float4*)(bp);
        float4 b1 = *(const float4*)(bp + 16 * 128);

        __syncthreads();   // previous iteration's smem reads done
        sA[la_r][la_k4 + 0] = a0.x; sA[la_r][la_k4 + 1] = a0.y;
        sA[la_r][la_k4 + 2] = a0.z; sA[la_r][la_k4 + 3] = a0.w;
        sA[la_r][la_k4 + 16] = a1.x; sA[la_r][la_k4 + 17] = a1.y;
        sA[la_r][la_k4 + 18] = a1.z; sA[la_r][la_k4 + 19] = a1.w;
        *(float4*)&sB[lb_k][lb_c4]      = b0;
        *(float4*)&sB[lb_k + 16][lb_c4] = b1;
        __syncthreads();

        #pragma unroll
        for (int kk = 0; kk < 32; kk++) {
            float av[4];
            #pragma unroll
            for (int i = 0; i < 4; i++) av[i] = sA[tr + 16 * i][kk];
            float4 bv = *(const float4*)&sB[kk][tc * 4];
            #pragma unroll
            for (int i = 0; i < 4; i++) {
                acc[i][0] += av[i] * bv.x;
                acc[i][1] += av[i] * bv.y;
                acc[i][2] += av[i] * bv.z;
                acc[i][3] += av[i] * bv.w;
            }
        }
    }

    #pragma unroll
    for (int i = 0; i < 4; i++) {
        int row = rowBase + tr + 16 * i;
        int col0 = cBase + tc * 4;
        float vv[4];
        #pragma unroll
        for (int j = 0; j < 4; j++) {
            float x = acc[i][j];
            if (bias) x += bias[col0 + j];
            if (comb) x = 0.5f * (x + comb[(size_t)row * 128 + col0 + j]);
            vv[j] = x;
        }
        *(float4*)(C + (size_t)row * 128 + col0) = make_float4(vv[0], vv[1], vv[2], vv[3]);
    }
}

__global__ __launch_bounds__(256) void k_gemm_h1(const float* __restrict__ f,
                                                 const float* __restrict__ W1) {
    gemm_body(f, 256, 256, W1, nullptr, nullptr, g_H1);
}
__global__ __launch_bounds__(256) void k_gemm_u1(const float* __restrict__ b1) {
    gemm_body(g_adj, NN, NN, g_H1, b1, nullptr, g_U1);
}
__global__ __launch_bounds__(256) void k_gemm_h2(const float* __restrict__ W2) {
    gemm_body(g_U1, 128, 128, W2, nullptr, nullptr, g_H2);
}
__global__ __launch_bounds__(256) void k_gemm_out(const float* __restrict__ b2,
                                                  float* __restrict__ out) {
    gemm_body(g_adj, NN, NN, g_H2, b2, g_U1, out);
}

// ---------------- launch ----------------------------------------------------
extern "C" void kernel_launch(void* const* d_in, const int* in_sizes, int n_in,
                              void* d_out, int out_size) {
    const float* feature = (const float*)d_in[0];
    const float* A1 = (const float*)d_in[1];
    const float* A2 = (const float*)d_in[2];
    const float* A3 = (const float*)d_in[3];
    const float* T1 = (const float*)d_in[4];
    const float* T2 = (const float*)d_in[5];
    const float* T3 = (const float*)d_in[6];
    const float* wb = (const float*)d_in[7];
    const float* W1 = (const float*)d_in[8];
    const float* b1 = (const float*)d_in[9];
    const float* W2 = (const float*)d_in[10];
    const float* b2 = (const float*)d_in[11];

    float* out = (float*)d_out;                      // output: 8192*128
    float* feat_out = out + (size_t)NN * NOUT;       // A1f, A2f, A3f: 3 * 8192*10

    int nfeat = 3 * NN * 10;
    k_zero<<<(nfeat + 255) / 256, 256>>>(feat_out, nfeat);

    dim3 gb(128, 128);
    k_build<<<gb, 256>>>(A1, A2, A3, T1, T2, T3, wb, feat_out);

    dim3 gg(128, 2);
    k_gemm_h1<<<gg, 256>>>(feature, W1);
    k_gemm_u1<<<gg, 256>>>(b1);
    k_gemm_h2<<<gg, 256>>>(W2);
    k_gemm_out<<<gg, 256>>>(b2, out);
}